// round 1
// baseline (speedup 1.0000x reference)
#include <cuda_runtime.h>
#include <cuda_bf16.h>

// EmbeddingsAverage: out[b,o] = (sum_{t<len[b]} x[b,t,:] / len[b]) . W[o,:] + bias[o]
// x: [64, 2048, 1024] f32, lengths: [64] i64-or-i32, W: [8, 1024] f32, bias: [8] f32
// out: [64, 8] f32

#define Bq   64
#define Tq   2048
#define Dq   1024
#define OUTq 8
#define SPLITS 16
#define ROWS (Tq / SPLITS)   // 128 time rows per split
#define THREADS 256          // 256 * float4 = 1024 = D

// Phase-1 scratch: per (b, split) partial sums over D. 64*16*1024*4B = 4 MB.
__device__ float g_partial[Bq * SPLITS * Dq];

// lengths dtype detection: if int64 (little-endian), word[1] is the high word
// of lengths[0] == 0 (lengths <= 2048). If int32, word[1] == lengths[1] >= 1.
__device__ __forceinline__ int load_len(const void* lenp, int b) {
    const unsigned* u = (const unsigned*)lenp;
    if (u[1] == 0u) {
        // int64 layout: low word at index 2*b
        return (int)u[2 * b];
    } else {
        return (int)((const int*)lenp)[b];
    }
}

__global__ void __launch_bounds__(THREADS)
partial_sum_kernel(const float* __restrict__ x, const void* __restrict__ lenp) {
    const int b = blockIdx.x;
    const int s = blockIdx.y;
    const int tid = threadIdx.x;

    const int len = load_len(lenp, b);
    const int t0 = s * ROWS;
    const int t1 = min(t0 + ROWS, len);
    const int n  = t1 - t0;          // may be <= 0

    float4 acc = make_float4(0.f, 0.f, 0.f, 0.f);

    // base: row t0 of batch b, this thread's float4 lane
    const float4* __restrict__ xp =
        (const float4*)(x + ((long long)b * Tq + t0) * Dq) + tid;
    const int rowstride = Dq / 4;    // float4 units per time row

    int t = 0;
    // 4-row unroll: 4 independent float4 loads in flight per thread
    for (; t + 4 <= n; t += 4) {
        float4 a0 = xp[(long long)(t + 0) * rowstride];
        float4 a1 = xp[(long long)(t + 1) * rowstride];
        float4 a2 = xp[(long long)(t + 2) * rowstride];
        float4 a3 = xp[(long long)(t + 3) * rowstride];
        acc.x += a0.x + a1.x + a2.x + a3.x;
        acc.y += a0.y + a1.y + a2.y + a3.y;
        acc.z += a0.z + a1.z + a2.z + a3.z;
        acc.w += a0.w + a1.w + a2.w + a3.w;
    }
    for (; t < n; t++) {
        float4 a0 = xp[(long long)t * rowstride];
        acc.x += a0.x; acc.y += a0.y; acc.z += a0.z; acc.w += a0.w;
    }

    // direct store (no atomics, no pre-zeroing needed)
    ((float4*)g_partial)[((b * SPLITS) + s) * rowstride + tid] = acc;
}

__global__ void __launch_bounds__(THREADS)
finish_kernel(const void* __restrict__ lenp,
              const float* __restrict__ W,
              const float* __restrict__ bias,
              float* __restrict__ out) {
    const int b = blockIdx.x;
    const int tid = threadIdx.x;
    const int lane = tid & 31;
    const int warp = tid >> 5;
    const int rowstride = Dq / 4;

    // reduce the 16 partials for this thread's float4 lane
    float4 sum = make_float4(0.f, 0.f, 0.f, 0.f);
    const float4* __restrict__ pp = (const float4*)g_partial + (b * SPLITS) * rowstride + tid;
#pragma unroll
    for (int s = 0; s < SPLITS; s++) {
        float4 p = pp[s * rowstride];
        sum.x += p.x; sum.y += p.y; sum.z += p.z; sum.w += p.w;
    }

    const float inv = 1.0f / (float)load_len(lenp, b);
    sum.x *= inv; sum.y *= inv; sum.z *= inv; sum.w *= inv;

    // 8-wide dot with W rows (W is [8, 1024] row-major; L2-resident, 32 KB)
    float acc[OUTq];
#pragma unroll
    for (int o = 0; o < OUTq; o++) {
        float4 w = ((const float4*)W)[o * rowstride + tid];
        acc[o] = sum.x * w.x + sum.y * w.y + sum.z * w.z + sum.w * w.w;
    }

    // warp-level reduce each of the 8 accumulators
#pragma unroll
    for (int o = 0; o < OUTq; o++) {
#pragma unroll
        for (int off = 16; off > 0; off >>= 1)
            acc[o] += __shfl_down_sync(0xffffffffu, acc[o], off);
    }

    __shared__ float sh[THREADS / 32][OUTq];   // [8 warps][8 outputs]
    if (lane == 0) {
#pragma unroll
        for (int o = 0; o < OUTq; o++) sh[warp][o] = acc[o];
    }
    __syncthreads();

    if (tid < OUTq) {
        float r = bias[tid];
#pragma unroll
        for (int w = 0; w < THREADS / 32; w++) r += sh[w][tid];
        out[b * OUTq + tid] = r;
    }
}

extern "C" void kernel_launch(void* const* d_in, const int* in_sizes, int n_in,
                              void* d_out, int out_size) {
    const float* x    = (const float*)d_in[0];
    const void*  lens = (const void*)d_in[1];
    const float* W    = (const float*)d_in[2];
    const float* bias = (const float*)d_in[3];
    float* out        = (float*)d_out;

    dim3 grid1(Bq, SPLITS);
    partial_sum_kernel<<<grid1, THREADS>>>(x, lens);
    finish_kernel<<<Bq, THREADS>>>(lens, W, bias, out);
}

// round 2
// speedup vs baseline: 1.0117x; 1.0117x over previous
#include <cuda_runtime.h>
#include <cuda_bf16.h>

// EmbeddingsAverage: out[b,o] = (sum_{t<len[b]} x[b,t,:] / len[b]) . W[o,:] + bias[o]
// x: [64, 2048, 1024] f32, lengths: [64] i64-or-i32, W: [8, 1024] f32, bias: [8] f32
// out: [64, 8] f32

#define Bq   64
#define Tq   2048
#define Dq   1024
#define OUTq 8
#define SPLITS 32
#define ROWS (Tq / SPLITS)   // 64 time rows per split
#define THREADS 256          // 256 * float4 = 1024 = D

// Phase-1 scratch: projected partials per (b, split, out). 64*32*8*4B = 64 KB.
__device__ float g_pout[Bq * SPLITS * OUTq];

// lengths dtype detection: if int64 (little-endian), word[1] is the high word
// of lengths[0] == 0 (lengths <= 2048). If int32, word[1] == lengths[1] >= 1.
__device__ __forceinline__ int load_len(const void* lenp, int b) {
    const unsigned* u = (const unsigned*)lenp;
    if (u[1] == 0u) {
        return (int)u[2 * b];            // int64 layout: low word at 2*b
    } else {
        return (int)((const int*)lenp)[b];
    }
}

__global__ void __launch_bounds__(THREADS)
partial_proj_kernel(const float* __restrict__ x,
                    const void* __restrict__ lenp,
                    const float* __restrict__ W) {
    const int b = blockIdx.x;
    const int s = blockIdx.y;
    const int tid = threadIdx.x;
    const int lane = tid & 31;
    const int warp = tid >> 5;
    const int rowstride = Dq / 4;        // float4 units per time row

    const int len = load_len(lenp, b);
    const int t0 = s * ROWS;
    const int n  = min(t0 + ROWS, len) - t0;   // may be <= 0

    float4 acc = make_float4(0.f, 0.f, 0.f, 0.f);

    const float4* __restrict__ xp =
        (const float4*)(x + ((long long)b * Tq + t0) * Dq) + tid;

    int t = 0;
    for (; t + 4 <= n; t += 4) {
        float4 a0 = xp[(t + 0) * rowstride];
        float4 a1 = xp[(t + 1) * rowstride];
        float4 a2 = xp[(t + 2) * rowstride];
        float4 a3 = xp[(t + 3) * rowstride];
        acc.x += a0.x + a1.x + a2.x + a3.x;
        acc.y += a0.y + a1.y + a2.y + a3.y;
        acc.z += a0.z + a1.z + a2.z + a3.z;
        acc.w += a0.w + a1.w + a2.w + a3.w;
    }
    for (; t < n; t++) {
        float4 a0 = xp[t * rowstride];
        acc.x += a0.x; acc.y += a0.y; acc.z += a0.z; acc.w += a0.w;
    }

    // Project this thread's D-lane partial onto the 8 W rows (W L2-resident).
    float po[OUTq];
#pragma unroll
    for (int o = 0; o < OUTq; o++) {
        float4 w = ((const float4*)W)[o * rowstride + tid];
        po[o] = acc.x * w.x + acc.y * w.y + acc.z * w.z + acc.w * w.w;
    }

    // Block-reduce 8 accumulators: warp shuffle, then cross-warp via smem.
#pragma unroll
    for (int o = 0; o < OUTq; o++) {
#pragma unroll
        for (int off = 16; off > 0; off >>= 1)
            po[o] += __shfl_down_sync(0xffffffffu, po[o], off);
    }

    __shared__ float sh[THREADS / 32][OUTq];
    if (lane == 0) {
#pragma unroll
        for (int o = 0; o < OUTq; o++) sh[warp][o] = po[o];
    }
    __syncthreads();

    if (tid < OUTq) {
        float r = 0.f;
#pragma unroll
        for (int w = 0; w < THREADS / 32; w++) r += sh[w][tid];
        g_pout[((b * SPLITS) + s) * OUTq + tid] = r;
    }
}

// One block: 512 threads = 64 batches x 8 outputs. Reads 64 KB scratch.
__global__ void __launch_bounds__(512)
finish_kernel(const void* __restrict__ lenp,
              const float* __restrict__ bias,
              float* __restrict__ out) {
    const int tid = threadIdx.x;          // tid = b * 8 + o
    const int b = tid >> 3;
    const int o = tid & 7;

    float sum = 0.f;
    const float* __restrict__ pp = g_pout + (b * SPLITS) * OUTq + o;
#pragma unroll
    for (int s = 0; s < SPLITS; s++) sum += pp[s * OUTq];

    const float inv = 1.0f / (float)load_len(lenp, b);
    out[tid] = sum * inv + bias[o];
}

extern "C" void kernel_launch(void* const* d_in, const int* in_sizes, int n_in,
                              void* d_out, int out_size) {
    const float* x    = (const float*)d_in[0];
    const void*  lens = (const void*)d_in[1];
    const float* W    = (const float*)d_in[2];
    const float* bias = (const float*)d_in[3];
    float* out        = (float*)d_out;

    dim3 grid1(Bq, SPLITS);
    partial_proj_kernel<<<grid1, THREADS>>>(x, lens, W);
    finish_kernel<<<1, 512>>>(lens, bias, out);
}